// round 14
// baseline (speedup 1.0000x reference)
#include <cuda_runtime.h>
#include <cuda_bf16.h>
#include <math.h>

#define NTOK 4096
#define DDIM 1024
#define NEXP 8
#define CAP  1280
#define NASSIGN (2 * NTOK)          // 8192 (k-major: p = k*NTOK + n)
#define NSLOT (NEXP * CAP)          // 10240
#define ROWF  (NEXP * CAP)          // 10240 floats per token row

// Output layout (fp32, concatenated in reference return order)
#define W_OFF 0ULL
#define M_OFF 41943040ULL
#define B_OFF 83886080ULL
#define L_OFF 94371840ULL

// Fill chunking: W tokens [0,2048), W [2048,4096), M [0,2048), M [2048,4096)
#define HALF_FLOATS (2048ULL * ROWF)            // 20,971,520 floats per half-region
#define HALF_VEC4   (HALF_FLOATS / 4)           // 5,242,880 float4

// Scratch (device globals; no allocations allowed)
__device__ int   g_topi[NTOK * 2];
__device__ float g_topp[NTOK * 2];
__device__ int   g_sidx[NASSIGN];   // flat idx into W region (or -1), p = k*NTOK+n
__device__ float g_sw[NASSIGN];     // weight for that entry
__device__ int   g_slot[NSLOT];

static cudaStream_t g_s1;           // LOW priority: fills (no deps, pure slack-free stores)
static cudaStream_t g_s2;           // HIGH priority: routing chain (short critical path)
static cudaEvent_t  g_evFork, g_evJoin, g_ev[4];
namespace {
struct StreamInit {
    StreamInit() {
        int lo = 0, hi = 0;
        cudaDeviceGetStreamPriorityRange(&lo, &hi);   // hi = numerically least
        cudaStreamCreateWithPriority(&g_s1, cudaStreamNonBlocking, lo);
        cudaStreamCreateWithPriority(&g_s2, cudaStreamNonBlocking, hi);
        cudaEventCreateWithFlags(&g_evFork, cudaEventDisableTiming);
        cudaEventCreateWithFlags(&g_evJoin, cudaEventDisableTiming);
        for (int i = 0; i < 4; i++)
            cudaEventCreateWithFlags(&g_ev[i], cudaEventDisableTiming);
    }
} g_streamInit;
}

// ---------------------------------------------------------------------------
// 1) Fused router logits + top-2 + softmax. One warp per token, float4 I/O.
// ---------------------------------------------------------------------------
__global__ void logits_top2_kernel(const float* __restrict__ x,
                                   const float* __restrict__ w,
                                   float* __restrict__ out)
{
    __shared__ float4 sw4[NEXP * 256];          // 32 KB, [e][d4]
    {
        const float4* w4 = reinterpret_cast<const float4*>(w);
        for (int i = threadIdx.x; i < NEXP * 256; i += blockDim.x)
            sw4[i] = w4[i];
    }
    __syncthreads();

    const int warp = threadIdx.x >> 5;
    const int lane = threadIdx.x & 31;
    const int n = blockIdx.x * (blockDim.x >> 5) + warp;   // token
    if (n >= NTOK) return;

    const float4* xr4 = reinterpret_cast<const float4*>(x + (size_t)n * DDIM);
    float acc[NEXP];
    #pragma unroll
    for (int e = 0; e < NEXP; e++) acc[e] = 0.f;

    #pragma unroll
    for (int i = 0; i < 8; i++) {
        const int d4 = i * 32 + lane;
        float4 xv = xr4[d4];
        #pragma unroll
        for (int e = 0; e < NEXP; e++) {
            float4 wv = sw4[e * 256 + d4];
            acc[e] = fmaf(xv.x, wv.x, acc[e]);
            acc[e] = fmaf(xv.y, wv.y, acc[e]);
            acc[e] = fmaf(xv.z, wv.z, acc[e]);
            acc[e] = fmaf(xv.w, wv.w, acc[e]);
        }
    }
    #pragma unroll
    for (int off = 16; off > 0; off >>= 1) {
        #pragma unroll
        for (int e = 0; e < NEXP; e++)
            acc[e] += __shfl_xor_sync(0xffffffffu, acc[e], off);
    }
    if (lane < NEXP)
        out[L_OFF + (size_t)n * NEXP + lane] = acc[lane];

    if (lane == 0) {
        int i0 = 0; float b0 = acc[0];
        #pragma unroll
        for (int e = 1; e < NEXP; e++)
            if (acc[e] > b0) { b0 = acc[e]; i0 = e; }
        int i1 = -1; float b1 = -INFINITY;
        #pragma unroll
        for (int e = 0; e < NEXP; e++)
            if (e != i0 && acc[e] > b1) { b1 = acc[e]; i1 = e; }
        float e1 = __expf(b1 - b0);
        float inv = 1.0f / (1.0f + e1);
        g_topi[n * 2 + 0] = i0;
        g_topi[n * 2 + 1] = i1;
        g_topp[n * 2 + 0] = inv;
        g_topp[n * 2 + 1] = e1 * inv;
    }
}

// ---------------------------------------------------------------------------
// 2) Fused rank + slot map + packed scatter list. One block per expert;
//    deterministic k-major exclusive prefix scan.
// ---------------------------------------------------------------------------
__global__ void rank_slot_kernel()
{
    const int e = blockIdx.x;           // expert
    const int t = threadIdx.x;          // 1024 threads
    const int PER = NASSIGN / 1024;     // 8 positions per thread

    if (t < CAP) g_slot[e * CAP + t] = -1;
    if (t + 1024 < CAP) g_slot[e * CAP + t + 1024] = -1;

    int flag[8];
    int local[8];
    int cnt = 0;
    #pragma unroll
    for (int i = 0; i < PER; i++) {
        int p = t * PER + i;
        int k = p >> 12;
        int n = p & (NTOK - 1);
        int ex = g_topi[n * 2 + k];
        flag[i] = (ex == e);
        local[i] = cnt;
        cnt += flag[i];
    }

    __shared__ int s[1024];
    s[t] = cnt;
    __syncthreads();
    #pragma unroll
    for (int off = 1; off < 1024; off <<= 1) {
        int vv = (t >= off) ? s[t - off] : 0;
        __syncthreads();
        s[t] += vv;
        __syncthreads();
    }
    int excl = s[t] - cnt;

    #pragma unroll
    for (int i = 0; i < PER; i++) {
        if (flag[i]) {
            int p = t * PER + i;
            int k = p >> 12;
            int n = p & (NTOK - 1);
            int r = excl + local[i];
            if (r < CAP) {
                g_sidx[p] = n * ROWF + e * CAP + r;
                g_sw[p]   = g_topp[n * 2 + k];
                g_slot[e * CAP + r] = n;
            } else {
                g_sidx[p] = -1;
            }
        }
    }
}

// ---------------------------------------------------------------------------
// 3) expert_batches: slot (e,c) = verbatim x-row copy or zeros.
// ---------------------------------------------------------------------------
__global__ void gather_kernel(const float* __restrict__ x,
                              float* __restrict__ out)
{
    int slot = blockIdx.x;              // 0..NSLOT-1
    int n = g_slot[slot];
    float4* dst = reinterpret_cast<float4*>(out + B_OFF + (size_t)slot * DDIM);
    if (n >= 0) {
        const float4* src = reinterpret_cast<const float4*>(x + (size_t)n * DDIM);
        __stcs(dst + threadIdx.x, src[threadIdx.x]);
    } else {
        __stcs(dst + threadIdx.x, make_float4(0.f, 0.f, 0.f, 0.f));
    }
}

// ---------------------------------------------------------------------------
// 4) Chunked zero-fill with evict-first streaming stores.
// ---------------------------------------------------------------------------
__global__ void fill_cs_kernel(float4* __restrict__ base)
{
    const float4 z = make_float4(0.f, 0.f, 0.f, 0.f);
    size_t stride = (size_t)gridDim.x * blockDim.x;
    for (size_t c = (size_t)blockIdx.x * blockDim.x + threadIdx.x;
         c < HALF_VEC4; c += stride)
        __stcs(base + c, z);
}

// ---------------------------------------------------------------------------
// 5) Sparse scatters: all weights at once; masks per token-half.
// ---------------------------------------------------------------------------
__global__ void scatter_w_all_kernel(float* __restrict__ out)
{
    int p = blockIdx.x * blockDim.x + threadIdx.x;
    if (p >= NASSIGN) return;
    int idx = g_sidx[p];
    if (idx >= 0) out[W_OFF + (size_t)idx] = g_sw[p];
}

__global__ void scatter_m_kernel(float* __restrict__ out, int n0)
{
    int t = blockIdx.x * blockDim.x + threadIdx.x;
    if (t >= 2 * 2048) return;
    int p = (t >> 11) * NTOK + n0 + (t & 2047);
    int idx = g_sidx[p];
    if (idx >= 0) out[M_OFF + (size_t)idx] = 1.0f;
}

extern "C" void kernel_launch(void* const* d_in, const int* in_sizes, int n_in,
                              void* d_out, int out_size)
{
    const float* x = (const float*)d_in[0];       // [2,2048,1024]
    const float* w = (const float*)d_in[1];       // [8,1024]
    float* out = (float*)d_out;
    float4* out4 = (float4*)d_out;

    cudaEventRecord(g_evFork, 0);
    cudaStreamWaitEvent(g_s1, g_evFork, 0);
    cudaStreamWaitEvent(g_s2, g_evFork, 0);

    // LOW priority: chunked zero-fill (52us of mandatory stores, no deps).
    fill_cs_kernel<<<4096, 256, 0, g_s1>>>(out4 + 0 * HALF_VEC4);   // W tokens [0,2048)
    cudaEventRecord(g_ev[0], g_s1);
    fill_cs_kernel<<<4096, 256, 0, g_s1>>>(out4 + 1 * HALF_VEC4);   // W tokens [2048,4096)
    cudaEventRecord(g_ev[1], g_s1);
    fill_cs_kernel<<<4096, 256, 0, g_s1>>>(out4 + 2 * HALF_VEC4);   // M tokens [0,2048)
    cudaEventRecord(g_ev[2], g_s1);
    fill_cs_kernel<<<4096, 256, 0, g_s1>>>(out4 + 3 * HALF_VEC4);   // M tokens [2048,4096)
    cudaEventRecord(g_ev[3], g_s1);

    // HIGH priority: short routing chain — must not be starved.
    logits_top2_kernel<<<512, 256, 0, g_s2>>>(x, w, out);
    rank_slot_kernel<<<NEXP, 1024, 0, g_s2>>>();
    gather_kernel<<<NSLOT, 256, 0, g_s2>>>(x, out);

    // Pipelined sparse scatters (on g_s2), each gated by its zeroed region.
    cudaStreamWaitEvent(g_s2, g_ev[1], 0);
    scatter_w_all_kernel<<<32, 256, 0, g_s2>>>(out);   // whole W region zeroed
    cudaStreamWaitEvent(g_s2, g_ev[2], 0);
    scatter_m_kernel<<<16, 256, 0, g_s2>>>(out, 0);
    cudaStreamWaitEvent(g_s2, g_ev[3], 0);
    scatter_m_kernel<<<16, 256, 0, g_s2>>>(out, 2048); // tiny tail

    // Join everything back to the capture-origin stream.
    cudaEventRecord(g_evJoin, g_s2);
    cudaStreamWaitEvent(0, g_evJoin, 0);
}

// round 15
// speedup vs baseline: 1.0827x; 1.0827x over previous
#include <cuda_runtime.h>
#include <cuda_bf16.h>
#include <math.h>

#define NTOK 4096
#define DDIM 1024
#define NEXP 8
#define CAP  1280
#define NASSIGN (2 * NTOK)          // 8192 (k-major: p = k*NTOK + n)
#define NSLOT (NEXP * CAP)          // 10240
#define ROWF  (NEXP * CAP)          // 10240 floats per token row

// Output layout (fp32, concatenated in reference return order)
#define W_OFF 0ULL
#define M_OFF 41943040ULL
#define B_OFF 83886080ULL
#define L_OFF 94371840ULL
#define WM_VEC4 20971520ULL         // (W+M) floats / 4

// Scratch (device globals; no allocations allowed)
__device__ int   g_topi[NTOK * 2];
__device__ float g_topp[NTOK * 2];
__device__ int   g_sidx[NASSIGN];   // flat idx into W region (or -1), p = k*NTOK+n
__device__ float g_sw[NASSIGN];     // weight for that entry
__device__ int   g_slot[NSLOT];

static cudaStream_t g_s1;           // fill + PDL scatter
static cudaStream_t g_s2;           // routing chain
static cudaEvent_t  g_evFork, g_evRank, g_evJ1, g_evJ2;
namespace {
struct StreamInit {
    StreamInit() {
        cudaStreamCreateWithFlags(&g_s1, cudaStreamNonBlocking);
        cudaStreamCreateWithFlags(&g_s2, cudaStreamNonBlocking);
        cudaEventCreateWithFlags(&g_evFork, cudaEventDisableTiming);
        cudaEventCreateWithFlags(&g_evRank, cudaEventDisableTiming);
        cudaEventCreateWithFlags(&g_evJ1, cudaEventDisableTiming);
        cudaEventCreateWithFlags(&g_evJ2, cudaEventDisableTiming);
    }
} g_streamInit;
}

// ---------------------------------------------------------------------------
// 1) Fused router logits + top-2 + softmax. One warp per token, float4 I/O.
// ---------------------------------------------------------------------------
__global__ void logits_top2_kernel(const float* __restrict__ x,
                                   const float* __restrict__ w,
                                   float* __restrict__ out)
{
    __shared__ float4 sw4[NEXP * 256];          // 32 KB, [e][d4]
    {
        const float4* w4 = reinterpret_cast<const float4*>(w);
        for (int i = threadIdx.x; i < NEXP * 256; i += blockDim.x)
            sw4[i] = w4[i];
    }
    __syncthreads();

    const int warp = threadIdx.x >> 5;
    const int lane = threadIdx.x & 31;
    const int n = blockIdx.x * (blockDim.x >> 5) + warp;   // token
    if (n >= NTOK) return;

    const float4* xr4 = reinterpret_cast<const float4*>(x + (size_t)n * DDIM);
    float acc[NEXP];
    #pragma unroll
    for (int e = 0; e < NEXP; e++) acc[e] = 0.f;

    #pragma unroll
    for (int i = 0; i < 8; i++) {
        const int d4 = i * 32 + lane;
        float4 xv = xr4[d4];
        #pragma unroll
        for (int e = 0; e < NEXP; e++) {
            float4 wv = sw4[e * 256 + d4];
            acc[e] = fmaf(xv.x, wv.x, acc[e]);
            acc[e] = fmaf(xv.y, wv.y, acc[e]);
            acc[e] = fmaf(xv.z, wv.z, acc[e]);
            acc[e] = fmaf(xv.w, wv.w, acc[e]);
        }
    }
    #pragma unroll
    for (int off = 16; off > 0; off >>= 1) {
        #pragma unroll
        for (int e = 0; e < NEXP; e++)
            acc[e] += __shfl_xor_sync(0xffffffffu, acc[e], off);
    }
    if (lane < NEXP)
        out[L_OFF + (size_t)n * NEXP + lane] = acc[lane];

    if (lane == 0) {
        int i0 = 0; float b0 = acc[0];
        #pragma unroll
        for (int e = 1; e < NEXP; e++)
            if (acc[e] > b0) { b0 = acc[e]; i0 = e; }
        int i1 = -1; float b1 = -INFINITY;
        #pragma unroll
        for (int e = 0; e < NEXP; e++)
            if (e != i0 && acc[e] > b1) { b1 = acc[e]; i1 = e; }
        float e1 = __expf(b1 - b0);
        float inv = 1.0f / (1.0f + e1);
        g_topi[n * 2 + 0] = i0;
        g_topi[n * 2 + 1] = i1;
        g_topp[n * 2 + 0] = inv;
        g_topp[n * 2 + 1] = e1 * inv;
    }
}

// ---------------------------------------------------------------------------
// 2) Fused rank + slot map + packed scatter list. One block per expert;
//    deterministic k-major exclusive prefix scan.
// ---------------------------------------------------------------------------
__global__ void rank_slot_kernel()
{
    const int e = blockIdx.x;           // expert
    const int t = threadIdx.x;          // 1024 threads
    const int PER = NASSIGN / 1024;     // 8 positions per thread

    if (t < CAP) g_slot[e * CAP + t] = -1;
    if (t + 1024 < CAP) g_slot[e * CAP + t + 1024] = -1;

    int flag[8];
    int local[8];
    int cnt = 0;
    #pragma unroll
    for (int i = 0; i < PER; i++) {
        int p = t * PER + i;
        int k = p >> 12;
        int n = p & (NTOK - 1);
        int ex = g_topi[n * 2 + k];
        flag[i] = (ex == e);
        local[i] = cnt;
        cnt += flag[i];
    }

    __shared__ int s[1024];
    s[t] = cnt;
    __syncthreads();
    #pragma unroll
    for (int off = 1; off < 1024; off <<= 1) {
        int vv = (t >= off) ? s[t - off] : 0;
        __syncthreads();
        s[t] += vv;
        __syncthreads();
    }
    int excl = s[t] - cnt;

    #pragma unroll
    for (int i = 0; i < PER; i++) {
        if (flag[i]) {
            int p = t * PER + i;
            int k = p >> 12;
            int n = p & (NTOK - 1);
            int r = excl + local[i];
            if (r < CAP) {
                g_sidx[p] = n * ROWF + e * CAP + r;
                g_sw[p]   = g_topp[n * 2 + k];
                g_slot[e * CAP + r] = n;
            } else {
                g_sidx[p] = -1;
            }
        }
    }
}

// ---------------------------------------------------------------------------
// 3) expert_batches: slot (e,c) = verbatim x-row copy or zeros.
// ---------------------------------------------------------------------------
__global__ void gather_kernel(const float* __restrict__ x,
                              float* __restrict__ out)
{
    int slot = blockIdx.x;              // 0..NSLOT-1
    int n = g_slot[slot];
    float4* dst = reinterpret_cast<float4*>(out + B_OFF + (size_t)slot * DDIM);
    if (n >= 0) {
        const float4* src = reinterpret_cast<const float4*>(x + (size_t)n * DDIM);
        __stcs(dst + threadIdx.x, src[threadIdx.x]);
    } else {
        __stcs(dst + threadIdx.x, make_float4(0.f, 0.f, 0.f, 0.f));
    }
}

// ---------------------------------------------------------------------------
// 4) Single monolithic zero-fill of W+M (R1's proven grid shape + __stcs).
// ---------------------------------------------------------------------------
__global__ void fill_kernel(float* __restrict__ out)
{
    const float4 z = make_float4(0.f, 0.f, 0.f, 0.f);
    float4* o = reinterpret_cast<float4*>(out);
    const size_t stride = (size_t)gridDim.x * blockDim.x;
    for (size_t c = (size_t)blockIdx.x * blockDim.x + threadIdx.x;
         c < WM_VEC4; c += stride)
        __stcs(o + c, z);
}

// ---------------------------------------------------------------------------
// 5) Fused W+M sparse scatter, launched with PDL after the fill on the same
//    stream. Preloads the packed lists BEFORE the grid-dependency sync so the
//    post-fill work is just the 16K stores (~1us), not launch+load latency.
// ---------------------------------------------------------------------------
__global__ void scatter_all_kernel(float* __restrict__ out)
{
    const int p = blockIdx.x * blockDim.x + threadIdx.x;   // 8192 entries
    int idx = -1;
    float wv = 0.f;
    if (p < NASSIGN) {
        idx = g_sidx[p];
        wv  = g_sw[p];
    }
    cudaGridDependencySynchronize();    // wait for fill completion
    if (idx >= 0) {
        out[W_OFF + (size_t)idx] = wv;
        out[M_OFF + (size_t)idx] = 1.0f;
    }
}

extern "C" void kernel_launch(void* const* d_in, const int* in_sizes, int n_in,
                              void* d_out, int out_size)
{
    const float* x = (const float*)d_in[0];       // [2,2048,1024]
    const float* w = (const float*)d_in[1];       // [8,1024]
    float* out = (float*)d_out;

    cudaEventRecord(g_evFork, 0);
    cudaStreamWaitEvent(g_s2, g_evFork, 0);
    cudaStreamWaitEvent(g_s1, g_evFork, 0);

    // Routing chain.
    logits_top2_kernel<<<512, 256, 0, g_s2>>>(x, w, out);
    rank_slot_kernel<<<NEXP, 1024, 0, g_s2>>>();
    cudaEventRecord(g_evRank, g_s2);
    gather_kernel<<<NSLOT, 256, 0, g_s2>>>(x, out);

    // Monolithic fill, then PDL scatter (needs rank too — long since done).
    fill_kernel<<<20480, 256, 0, g_s1>>>(out);
    cudaStreamWaitEvent(g_s1, g_evRank, 0);
    {
        cudaLaunchConfig_t cfg = {};
        cfg.gridDim = dim3(32, 1, 1);
        cfg.blockDim = dim3(256, 1, 1);
        cfg.dynamicSmemBytes = 0;
        cfg.stream = g_s1;
        cudaLaunchAttribute attr[1];
        attr[0].id = cudaLaunchAttributeProgrammaticStreamSerialization;
        attr[0].val.programmaticStreamSerializationAllowed = 1;
        cfg.attrs = attr;
        cfg.numAttrs = 1;
        cudaLaunchKernelEx(&cfg, scatter_all_kernel, out);
    }

    // Join both branches back to the capture-origin stream.
    cudaEventRecord(g_evJ1, g_s1);
    cudaEventRecord(g_evJ2, g_s2);
    cudaStreamWaitEvent(0, g_evJ1, 0);
    cudaStreamWaitEvent(0, g_evJ2, 0);
}